// round 6
// baseline (speedup 1.0000x reference)
#include <cuda_runtime.h>
#include <cuda_bf16.h>
#include <cstdint>

// 12-bit ripple-carry adder over float-encoded bits (exact {0.0,1.0} values).
// Bit 11 is LSB. Output: sums [BATCH,12] then carry [BATCH,1], float32.
//
// Integer-only path: float 1.0f == 0x3F800000, so bit j of a row is
// (word >> 23) & 1 with no F2I. Pack 12 bits -> uint, one IADD, unpack 13
// output words as bit * 0x3F800000 (no I2F). 2 rows/thread for MLP + wide
// carry stores; __ldcs/__stcs since every byte is touched exactly once.

__device__ __forceinline__ uint32_t pack12(uint4 u0, uint4 u1, uint4 u2)
{
    // element j (0..11) -> bit (11-j); source bit is bit 23 of each word.
    return ((u0.x >> 12) & 0x800u) | ((u0.y >> 13) & 0x400u) |
           ((u0.z >> 14) & 0x200u) | ((u0.w >> 15) & 0x100u) |
           ((u1.x >> 16) & 0x080u) | ((u1.y >> 17) & 0x040u) |
           ((u1.z >> 18) & 0x020u) | ((u1.w >> 19) & 0x010u) |
           ((u2.x >> 20) & 0x008u) | ((u2.y >> 21) & 0x004u) |
           ((u2.z >> 22) & 0x002u) | ((u2.w >> 23) & 0x001u);
}

__device__ __forceinline__ uint32_t fbit(uint32_t s, int p)
{
    return ((s >> p) & 1u) * 0x3F800000u;   // 0.0f or 1.0f as raw bits
}

__global__ __launch_bounds__(256) void adder12_kernel(
    const uint4* __restrict__ A4,
    const uint4* __restrict__ B4,
    uint4* __restrict__ S4,
    uint2* __restrict__ C2,
    int n_pairs)
{
    int t = blockIdx.x * blockDim.x + threadIdx.x;
    if (t >= n_pairs) return;

    const size_t base = (size_t)t * 6;   // 2 rows = 6 uint4 per input

    // Front-batched loads: 12 independent LDG.128 in flight.
    uint4 a0 = __ldcs(&A4[base + 0]);
    uint4 a1 = __ldcs(&A4[base + 1]);
    uint4 a2 = __ldcs(&A4[base + 2]);
    uint4 a3 = __ldcs(&A4[base + 3]);
    uint4 a4 = __ldcs(&A4[base + 4]);
    uint4 a5 = __ldcs(&A4[base + 5]);
    uint4 b0 = __ldcs(&B4[base + 0]);
    uint4 b1 = __ldcs(&B4[base + 1]);
    uint4 b2 = __ldcs(&B4[base + 2]);
    uint4 b3 = __ldcs(&B4[base + 3]);
    uint4 b4 = __ldcs(&B4[base + 4]);
    uint4 b5 = __ldcs(&B4[base + 5]);

    uint32_t s0 = pack12(a0, a1, a2) + pack12(b0, b1, b2);
    uint32_t s1 = pack12(a3, a4, a5) + pack12(b3, b4, b5);

    uint4 o;
    o.x = fbit(s0, 11); o.y = fbit(s0, 10); o.z = fbit(s0, 9);  o.w = fbit(s0, 8);
    __stcs(&S4[base + 0], o);
    o.x = fbit(s0, 7);  o.y = fbit(s0, 6);  o.z = fbit(s0, 5);  o.w = fbit(s0, 4);
    __stcs(&S4[base + 1], o);
    o.x = fbit(s0, 3);  o.y = fbit(s0, 2);  o.z = fbit(s0, 1);  o.w = fbit(s0, 0);
    __stcs(&S4[base + 2], o);
    o.x = fbit(s1, 11); o.y = fbit(s1, 10); o.z = fbit(s1, 9);  o.w = fbit(s1, 8);
    __stcs(&S4[base + 3], o);
    o.x = fbit(s1, 7);  o.y = fbit(s1, 6);  o.z = fbit(s1, 5);  o.w = fbit(s1, 4);
    __stcs(&S4[base + 4], o);
    o.x = fbit(s1, 3);  o.y = fbit(s1, 2);  o.z = fbit(s1, 1);  o.w = fbit(s1, 0);
    __stcs(&S4[base + 5], o);

    uint2 c;
    c.x = fbit(s0, 12);
    c.y = fbit(s1, 12);
    __stcs(&C2[t], c);
}

extern "C" void kernel_launch(void* const* d_in, const int* in_sizes, int n_in,
                              void* d_out, int out_size)
{
    const uint4* A4 = (const uint4*)d_in[0];
    const uint4* B4 = (const uint4*)d_in[1];
    float* out = (float*)d_out;

    const int n_rows = in_sizes[0] / 12;          // 4194304
    const int n_pairs = n_rows / 2;               // 2097152 (BATCH is even)

    uint4* S4 = (uint4*)out;                      // sums: n_rows * 12 floats
    uint2* C2 = (uint2*)(out + (size_t)n_rows * 12);  // carry: n_rows floats

    const int threads = 256;
    const int blocks = (n_pairs + threads - 1) / threads;
    adder12_kernel<<<blocks, threads>>>(A4, B4, S4, C2, n_pairs);
}

// round 7
// speedup vs baseline: 1.1735x; 1.1735x over previous
#include <cuda_runtime.h>
#include <cuda_bf16.h>
#include <cstdint>

// 12-bit ripple-carry adder over float-encoded bits (exact {0.0,1.0}).
// Bit 11 is LSB. Output: sums [BATCH,12] then carry [BATCH,1], float32.
//
// R7: revert to R1's 1-row/thread, default-cached loads (L1 hits on the
// 48B-strided pattern are load-bearing; __ldcs regressed DRAM 82.6->67.3%).
// Keep the integer-only bit path: pack tests bit 23 of 0x3F800000 words,
// unpack emits bit * 0x3F800000. No F2I/I2F anywhere.

__device__ __forceinline__ uint32_t pack12(uint4 u0, uint4 u1, uint4 u2)
{
    // element j (0..11) -> bit (11-j); source bit is bit 23 of each word.
    return ((u0.x >> 12) & 0x800u) | ((u0.y >> 13) & 0x400u) |
           ((u0.z >> 14) & 0x200u) | ((u0.w >> 15) & 0x100u) |
           ((u1.x >> 16) & 0x080u) | ((u1.y >> 17) & 0x040u) |
           ((u1.z >> 18) & 0x020u) | ((u1.w >> 19) & 0x010u) |
           ((u2.x >> 20) & 0x008u) | ((u2.y >> 21) & 0x004u) |
           ((u2.z >> 22) & 0x002u) | ((u2.w >> 23) & 0x001u);
}

__device__ __forceinline__ uint32_t fbit(uint32_t s, int p)
{
    return ((s >> p) & 1u) * 0x3F800000u;   // 0.0f or 1.0f as raw bits
}

__global__ __launch_bounds__(256) void adder12_kernel(
    const uint4* __restrict__ A4,
    const uint4* __restrict__ B4,
    uint4* __restrict__ S4,
    float* __restrict__ Cout,
    int n_rows)
{
    int r = blockIdx.x * blockDim.x + threadIdx.x;
    if (r >= n_rows) return;

    const size_t base = (size_t)r * 3;   // 1 row = 3 uint4 per input

    uint4 a0 = A4[base + 0];
    uint4 a1 = A4[base + 1];
    uint4 a2 = A4[base + 2];
    uint4 b0 = B4[base + 0];
    uint4 b1 = B4[base + 1];
    uint4 b2 = B4[base + 2];

    uint32_t s = pack12(a0, a1, a2) + pack12(b0, b1, b2);

    uint4 o;
    o.x = fbit(s, 11); o.y = fbit(s, 10); o.z = fbit(s, 9);  o.w = fbit(s, 8);
    S4[base + 0] = o;
    o.x = fbit(s, 7);  o.y = fbit(s, 6);  o.z = fbit(s, 5);  o.w = fbit(s, 4);
    S4[base + 1] = o;
    o.x = fbit(s, 3);  o.y = fbit(s, 2);  o.z = fbit(s, 1);  o.w = fbit(s, 0);
    S4[base + 2] = o;

    ((uint32_t*)Cout)[r] = fbit(s, 12);
}

extern "C" void kernel_launch(void* const* d_in, const int* in_sizes, int n_in,
                              void* d_out, int out_size)
{
    const uint4* A4 = (const uint4*)d_in[0];
    const uint4* B4 = (const uint4*)d_in[1];
    float* out = (float*)d_out;

    const int n_rows = in_sizes[0] / 12;          // 4194304

    uint4* S4 = (uint4*)out;                      // sums: n_rows * 12 floats
    float* Cout = out + (size_t)n_rows * 12;      // carry: n_rows floats

    const int threads = 256;
    const int blocks = (n_rows + threads - 1) / threads;
    adder12_kernel<<<blocks, threads>>>(A4, B4, S4, Cout, n_rows);
}